// round 5
// baseline (speedup 1.0000x reference)
#include <cuda_runtime.h>

#define NPTS    4096
#define NB      16
#define TPB     1024
#define QCHUNK  128
#define IPT     4
#define NQT     32                          // q-threads per slice (QCHUNK/IPT)
#define NSLICE  32                          // TPB / NQT
#define SLICE_QUADS (NPTS / NSLICE / 4)     // 32 quads = 128 points per slice
#define NITEMS  (2 * NB * (NPTS / QCHUNK))  // 1024
#define GRID    148

__device__ float g_accum;      // zero at entry/exit of every launch
__device__ unsigned g_count;   // zero at entry/exit of every launch

typedef unsigned long long u64;

static __device__ __forceinline__ u64 bcast2(float v) {
    u64 r;
    asm("mov.b64 %0, {%1, %1};" : "=l"(r) : "f"(v));
    return r;
}
static __device__ __forceinline__ void unpack2(u64 v, float &lo, float &hi) {
    asm("mov.b64 {%0, %1}, %2;" : "=f"(lo), "=f"(hi) : "l"(v));
}
static __device__ __forceinline__ u64 fma2(u64 a, u64 b, u64 c) {
    u64 d;
    asm("fma.rn.f32x2 %0, %1, %2, %3;" : "=l"(d) : "l"(a), "l"(b), "l"(c));
    return d;
}

// dist2(i,j) = |q_i|^2 + (|b_j|^2 - 2 q_i . b_j)
// inner loop: packed acc = u_j - 2*dot via 3 FFMA2 per 2 points (fma pipe),
// running min via FMNMX (alu pipe); |q|^2 added once at combine.
__global__ void __launch_bounds__(TPB) chamfer_main(const float* __restrict__ tpl,
                                                    const float* __restrict__ src,
                                                    float* __restrict__ out) {
    extern __shared__ float sm[];
    float* sx = sm;
    float* sy = sm + NPTS;
    float* sz = sm + 2 * NPTS;
    float* su = sm + 3 * NPTS;
    float* pmin = sm + 4 * NPTS;            // [NSLICE][QCHUNK] = 4096 floats

    const int tid   = threadIdx.x;
    const int qi    = tid & (NQT - 1);      // 0..31
    const int slice = tid >> 5;             // 0..31 (== warp id)

    const int lo = (int)(((long long)blockIdx.x * NITEMS) / GRID);
    const int hi = (int)(((long long)(blockIdx.x + 1) * NITEMS) / GRID);

    int cached_cloud = -1;
    float s = 0.0f;

    for (int item = lo; item < hi; item++) {
        const int qc    = item & 31;        // 32 qchunks per cloud
        const int cloud = item >> 5;
        const int batch = cloud & 15;
        const int dir   = cloud >> 4;

        const float* Q = (dir == 0) ? tpl : src;
        const float* D = (dir == 0) ? src : tpl;
        Q += (size_t)batch * NPTS * 3;
        D += (size_t)batch * NPTS * 3;

        if (cloud != cached_cloud) {
            for (int p = tid; p < NPTS; p += TPB) {
                float x = D[3 * p + 0], y = D[3 * p + 1], z = D[3 * p + 2];
                sx[p] = x; sy[p] = y; sz[p] = z;
                su[p] = x * x + y * y + z * z;
            }
            cached_cloud = cloud;
            __syncthreads();
        }

        const int qbase = qc * QCHUNK;

        u64 qx[IPT], qy[IPT], qz[IPT];
        float bA[IPT], bB[IPT];
#pragma unroll
        for (int k = 0; k < IPT; k++) {
            int q = qbase + k * NQT + qi;
            qx[k] = bcast2(-2.0f * Q[3 * q + 0]);
            qy[k] = bcast2(-2.0f * Q[3 * q + 1]);
            qz[k] = bcast2(-2.0f * Q[3 * q + 2]);
            bA[k] = 3.4e38f;
            bB[k] = 3.4e38f;
        }

        const ulonglong2* px = (const ulonglong2*)sx + slice * SLICE_QUADS;
#define PY_OFF (NPTS / 2 / 2)               // ulonglong2 stride between arrays
#pragma unroll 2
        for (int j = 0; j < SLICE_QUADS; j++) {
            ulonglong2 bx = px[j];
            ulonglong2 by = px[j + PY_OFF];
            ulonglong2 bz = px[j + 2 * PY_OFF];
            ulonglong2 bu = px[j + 3 * PY_OFF];
#pragma unroll
            for (int k = 0; k < IPT; k++) {
                u64 a01 = fma2(qz[k], bz.x, bu.x);
                a01 = fma2(qy[k], by.x, a01);
                a01 = fma2(qx[k], bx.x, a01);
                u64 a23 = fma2(qz[k], bz.y, bu.y);
                a23 = fma2(qy[k], by.y, a23);
                a23 = fma2(qx[k], bx.y, a23);
                float l0, h0, l1, h1;
                unpack2(a01, l0, h0);
                unpack2(a23, l1, h1);
                bA[k] = fminf(bA[k], fminf(l0, l1));
                bB[k] = fminf(bB[k], fminf(h0, h1));
            }
        }

#pragma unroll
        for (int k = 0; k < IPT; k++)
            pmin[slice * QCHUNK + k * NQT + qi] = fminf(bA[k], bB[k]);
        __syncthreads();

        // combine: threads 0..127 fold the 32 slices for their query
        if (tid < QCHUNK) {
            float m = pmin[tid];
#pragma unroll
            for (int sl = 1; sl < NSLICE; sl++)
                m = fminf(m, pmin[sl * QCHUNK + tid]);
            int qg = qbase + tid;
            float x = Q[3 * qg + 0], y = Q[3 * qg + 1], z = Q[3 * qg + 2];
            float c = x * x + y * y + z * z;
            s += sqrtf(fmaxf(c + m, 0.0f));
        }
        __syncthreads();   // pmin reuse / smem refill safety
    }

    // block reduction
#pragma unroll
    for (int o = 16; o; o >>= 1) s += __shfl_xor_sync(0xffffffffu, s, o);
    if ((tid & 31) == 0) pmin[tid >> 5] = s;
    __syncthreads();

    if (tid == 0) {
        float t = 0.0f;
#pragma unroll
        for (int w = 0; w < TPB / 32; w++) t += pmin[w];
        atomicAdd(&g_accum, t);
        __threadfence();
        unsigned old = atomicAdd(&g_count, 1u);
        if (old == GRID - 1) {
            __threadfence();
            float total = atomicAdd(&g_accum, 0.0f);   // atomic read
            out[0] = total * (1.0f / 131072.0f);       // / (2*16*4096)
            g_accum = 0.0f;                            // reset for next replay
            __threadfence();
            atomicExch(&g_count, 0u);
        }
    }
}

extern "C" void kernel_launch(void* const* d_in, const int* in_sizes, int n_in,
                              void* d_out, int out_size) {
    const float* tpl = (const float*)d_in[0];
    const float* src = (const float*)d_in[1];
    (void)in_sizes; (void)n_in; (void)out_size;

    const int smem = (4 * NPTS + NSLICE * QCHUNK) * (int)sizeof(float);
    cudaFuncSetAttribute(chamfer_main, cudaFuncAttributeMaxDynamicSharedMemorySize, smem);

    chamfer_main<<<GRID, TPB, smem>>>(tpl, src, (float*)d_out);
}